// round 15
// speedup vs baseline: 8.3683x; 1.0217x over previous
#include <cuda_runtime.h>
#include <cuda_bf16.h>
#include <cuda_fp16.h>
#include <math_constants.h>
#include <stdint.h>

// Problem constants
#define NB   2
#define C    256
#define A    3
#define KTOP 20
#define D    256
#define BOXC 12
#define SUMHW 13600   // 10240 + 2560 + 640 + 160
#define WSPL 294912   // per-layer conv split-weight u32 count
#define WDNS 32768    // dense 256x256 split-weight u32 count
#define STILE 54      // ceil(SUMHW/256)

// ---------------- scratch (device globals) ----------------------------------
__device__ float g_t2p[NB * C * SUMHW];
__device__ float g_cell[NB * SUMHW];
__device__ float g_cand_hid[NB * C * 80];
__device__ float g_cand_sc[NB * 80];
__device__ float g_pproj[NB * KTOP * D];
// split activations: [n][pair=128][SUMHW] u32
__device__ uint32_t g_sA_hi[NB * 128 * SUMHW];    // feats bf16 split (person)
__device__ uint32_t g_sA_lo[NB * 128 * SUMHW];
__device__ uint32_t g_sAf_hi[NB * 128 * SUMHW];   // feats fp16 split (object)
__device__ uint32_t g_sAf_lo[NB * 128 * SUMHW];
__device__ uint32_t g_sB_hi[NB * 128 * SUMHW];    // person conv1 out (bf16)
__device__ uint32_t g_sB_lo[NB * 128 * SUMHW];
__device__ uint32_t g_sD_hi[NB * 128 * SUMHW];    // object conv1 out (fp16)
__device__ uint32_t g_sD_lo[NB * 128 * SUMHW];
__device__ uint32_t g_sC_hi[NB * 128 * SUMHW];    // object conv2 out (fp16)
__device__ uint32_t g_sC_lo[NB * 128 * SUMHW];
__device__ uint32_t g_hs_hi[NB * 128 * SUMHW];    // hsum out (fp16)
__device__ uint32_t g_hs_lo[NB * 128 * SUMHW];
// split weights (fragment order)
__device__ uint32_t g_wsp_hi[4 * WSPL];   // layers 0,1 bf16 ; layers 2,3 fp16
__device__ uint32_t g_wsp_lo[4 * WSPL];
__device__ uint32_t g_wd_hi[2 * WDNS];    // fp16: 0: Wo, 1: rn2
__device__ uint32_t g_wd_lo[2 * WDNS];

// per-scale constants
__device__ __constant__ int cOFF[4]  = {0, 10240, 12800, 13440};
__device__ __constant__ int cHW[4]   = {10240, 2560, 640, 160};
__device__ __constant__ int cH[4]    = {80, 40, 20, 10};
__device__ __constant__ int cW[4]    = {128, 64, 32, 16};
__device__ __constant__ int cPLOG[4] = {0,      61440,  76800,  80640};
__device__ __constant__ int cPDEL[4] = {81600,  327360, 388800, 404160};
__device__ __constant__ int cOLOG[4] = {408000, 469440, 484800, 488640};
__device__ __constant__ int cODEL[4] = {489600, 735360, 796800, 812160};

__device__ __forceinline__ int scale_of(int p) {
    return (p < 10240) ? 0 : (p < 12800) ? 1 : (p < 13440) ? 2 : 3;
}

// ---------------- mma / split helpers ---------------------------------------
__device__ __forceinline__ void mma_bf16(float* c, const uint32_t* a, const uint32_t* b) {
    asm volatile(
        "mma.sync.aligned.m16n8k16.row.col.f32.bf16.bf16.f32 "
        "{%0,%1,%2,%3}, {%4,%5,%6,%7}, {%8,%9}, {%0,%1,%2,%3};\n"
        : "+f"(c[0]), "+f"(c[1]), "+f"(c[2]), "+f"(c[3])
        : "r"(a[0]), "r"(a[1]), "r"(a[2]), "r"(a[3]), "r"(b[0]), "r"(b[1]));
}
__device__ __forceinline__ void mma_f16(float* c, const uint32_t* a, const uint32_t* b) {
    asm volatile(
        "mma.sync.aligned.m16n8k16.row.col.f32.f16.f16.f32 "
        "{%0,%1,%2,%3}, {%4,%5,%6,%7}, {%8,%9}, {%0,%1,%2,%3};\n"
        : "+f"(c[0]), "+f"(c[1]), "+f"(c[2]), "+f"(c[3])
        : "r"(a[0]), "r"(a[1]), "r"(a[2]), "r"(a[3]), "r"(b[0]), "r"(b[1]));
}
__device__ __forceinline__ void split_pack(float v0, float v1,
                                           uint32_t& hi_out, uint32_t& lo_out) {
    __nv_bfloat16 h0 = __float2bfloat16(v0);
    __nv_bfloat16 h1 = __float2bfloat16(v1);
    __nv_bfloat16 l0 = __float2bfloat16(v0 - __bfloat162float(h0));
    __nv_bfloat16 l1 = __float2bfloat16(v1 - __bfloat162float(h1));
    hi_out = ((uint32_t)__bfloat16_as_ushort(h1) << 16) | (uint32_t)__bfloat16_as_ushort(h0);
    lo_out = ((uint32_t)__bfloat16_as_ushort(l1) << 16) | (uint32_t)__bfloat16_as_ushort(l0);
}
__device__ __forceinline__ void split_pack_h(float v0, float v1,
                                             uint32_t& hi_out, uint32_t& lo_out) {
    __half h0 = __float2half(v0);
    __half h1 = __float2half(v1);
    __half l0 = __float2half(v0 - __half2float(h0));
    __half l1 = __float2half(v1 - __half2float(h1));
    hi_out = ((uint32_t)__half_as_ushort(h1) << 16) | (uint32_t)__half_as_ushort(h0);
    lo_out = ((uint32_t)__half_as_ushort(l1) << 16) | (uint32_t)__half_as_ushort(l0);
}
// reconstruct pair from fp16 split word pair
__device__ __forceinline__ void unsplit_h(uint32_t hw, uint32_t lw, float& v0, float& v1) {
    v0 = __half2float(__ushort_as_half((unsigned short)(hw & 0xFFFF))) +
         __half2float(__ushort_as_half((unsigned short)(lw & 0xFFFF)));
    v1 = __half2float(__ushort_as_half((unsigned short)(hw >> 16))) +
         __half2float(__ushort_as_half((unsigned short)(lw >> 16)));
}
__device__ __forceinline__ uint32_t smem_addr_of(const void* p) {
    return (uint32_t)__cvta_generic_to_shared(p);
}
__device__ __forceinline__ void cp16(uint32_t dst, const void* src, bool pred) {
    asm volatile("cp.async.cg.shared.global [%0], [%1], 16, %2;"
                 :: "r"(dst), "l"(src), "r"(pred ? 16 : 0));
}
__device__ __forceinline__ void cp4(uint32_t dst, const void* src, bool pred) {
    asm volatile("cp.async.ca.shared.global [%0], [%1], 4, %2;"
                 :: "r"(dst), "l"(src), "r"(pred ? 4 : 0));
}
#define CP_COMMIT() asm volatile("cp.async.commit_group;" ::: "memory")
#define CP_WAIT(n)  asm volatile("cp.async.wait_group %0;" :: "n"(n) : "memory")

// ---------------- conv weight pre-split (fragment order) --------------------
__global__ __launch_bounds__(256)
void split_w_conv(const float* __restrict__ w0, const float* __restrict__ w1,
                  const float* __restrict__ w2, const float* __restrict__ w3,
                  uint32_t* __restrict__ outH, uint32_t* __restrict__ outL)
{
    const int i = blockIdx.x * 256 + threadIdx.x;
    if (i >= WSPL) return;
    const int layer = blockIdx.y;
    const float* w = (layer == 0) ? w0 : (layer == 1) ? w1 : (layer == 2) ? w2 : w3;
    const int e = i & 3;
    int j = i >> 2;
    const int slot = j & 31; j >>= 5;
    const int o4 = j & 3; j >>= 2;
    const int tap = j % 9; j /= 9;
    const int ocg = j & 3;
    const int q = j >> 2;
    const int g = ((slot >> 3) << 1) | (slot & 1);
    const int t = (slot >> 1) & 3;
    const int oc = ocg * 64 + o4 * 16 + g + (e & 1) * 8;
    const int p = t + ((e >> 1) << 2);
    const int ci0 = q * 16 + 2 * p;
    float v0 = w[(size_t)oc * 2304 + ci0 * 9 + tap];
    float v1 = w[(size_t)oc * 2304 + (ci0 + 1) * 9 + tap];
    uint32_t hi, lo;
    if (layer < 2) split_pack(v0, v1, hi, lo);
    else           split_pack_h(v0, v1, hi, lo);
    outH[(size_t)layer * WSPL + i] = hi;
    outL[(size_t)layer * WSPL + i] = lo;
}

// ---------------- dense weight pre-split (fp16, fragment order) -------------
__global__ __launch_bounds__(256)
void split_w_dense(const float* __restrict__ wA, const float* __restrict__ wB,
                   int strideA, int strideB,
                   uint32_t* __restrict__ outH, uint32_t* __restrict__ outL)
{
    const int i = blockIdx.x * 256 + threadIdx.x;
    if (i >= WDNS) return;
    const int which = blockIdx.y;
    const float* w = which ? wB : wA;
    const int stride = which ? strideB : strideA;
    const int e = i & 3;
    int j = i >> 2;
    const int slot = j & 31; j >>= 5;
    const int o4 = j & 3; j >>= 2;
    const int mg = j & 3;
    const int q = j >> 2;
    const int g = ((slot >> 3) << 1) | (slot & 1);
    const int t = (slot >> 1) & 3;
    const int m = mg * 64 + o4 * 16 + g + (e & 1) * 8;
    const int p = t + ((e >> 1) << 2);
    const int k0 = q * 16 + 2 * p;
    float v0 = w[(size_t)m * stride + k0];
    float v1 = w[(size_t)m * stride + k0 + 1];
    uint32_t hi, lo;
    split_pack_h(v0, v1, hi, lo);
    outH[(size_t)which * WDNS + i] = hi;
    outL[(size_t)which * WDNS + i] = lo;
}

// ---------------- feats pre-split (both formats) ----------------------------
__global__ __launch_bounds__(256)
void split_feats_kernel(const float* __restrict__ f0, const float* __restrict__ f1,
                        const float* __restrict__ f2, const float* __restrict__ f3,
                        uint32_t* __restrict__ outHb, uint32_t* __restrict__ outLb,
                        uint32_t* __restrict__ outHf, uint32_t* __restrict__ outLf)
{
    const int px = blockIdx.x * 256 + threadIdx.x;
    if (px >= SUMHW) return;
    const int c2 = blockIdx.y;
    const int n  = blockIdx.z;
    const int s = scale_of(px);
    const int ploc = px - cOFF[s];
    const int HW = cHW[s];
    const float* f = (s == 0) ? f0 : (s == 1) ? f1 : (s == 2) ? f2 : f3;
    const float* src = f + ((size_t)n * C + 2 * c2) * HW + ploc;
    float v0 = src[0], v1 = src[HW];
    const size_t o = ((size_t)n * 128 + c2) * SUMHW + px;
    uint32_t hi, lo;
    split_pack(v0, v1, hi, lo);
    outHb[o] = hi; outLb[o] = lo;
    split_pack_h(v0, v1, hi, lo);
    outHf[o] = hi; outLf[o] = lo;
}

// ---------------- conv3x3 dual-branch (validated core) ----------------------
// flags bit0: fp16 2-term compute; bit1: split output packed as fp16
#define IPAD 28
#define ST_IH 9216
#define ST_IL 11456
#define STG_U32 13696
#define CONV_SMEM (2 * STG_U32 * 4)   // 109568 B

__global__ __launch_bounds__(256, 2)
void conv3x3_dual(const uint32_t* __restrict__ in0H, const uint32_t* __restrict__ in0L,
                  const uint32_t* __restrict__ in1H, const uint32_t* __restrict__ in1L,
                  const uint32_t* __restrict__ wH0, const uint32_t* __restrict__ wL0,
                  const uint32_t* __restrict__ wH1, const uint32_t* __restrict__ wL1,
                  const float* __restrict__ bias0, const float* __restrict__ bias1,
                  float* __restrict__ dF0, uint32_t* __restrict__ dH0, uint32_t* __restrict__ dL0,
                  float* __restrict__ dF1, uint32_t* __restrict__ dH1, uint32_t* __restrict__ dL1,
                  int flags0, int flags1)
{
    extern __shared__ __align__(16) uint32_t smu[];
    __shared__ float s_bias[64];

    const int branch = blockIdx.z & 1;
    const int n = blockIdx.z >> 1;
    const uint32_t* inH = branch ? in1H : in0H;
    const uint32_t* inL = branch ? in1L : in0L;
    const uint32_t* wH  = branch ? wH1 : wH0;
    const uint32_t* wL  = branch ? wL1 : wL0;
    const float* bias   = branch ? bias1 : bias0;
    float* dstF    = branch ? dF1 : dF0;
    uint32_t* dstH = branch ? dH1 : dH0;
    uint32_t* dstL = branch ? dL1 : dL0;
    const int flags = branch ? flags1 : flags0;
    const bool f16c = (flags & 1) != 0;
    const bool sp16 = (flags & 2) != 0;

    const int bx = blockIdx.x;
    int s, t_;
    if (bx < 80)       { s = 0; t_ = bx; }
    else if (bx < 100) { s = 1; t_ = bx - 80; }
    else if (bx < 106) { s = 2; t_ = bx - 100; }
    else               { s = 3; t_ = bx - 106; }
    const int H = cH[s], W = cW[s];
    const int tilesX = W >> 4;
    const int ty = t_ / tilesX, tx = t_ % tilesX;
    const int h0 = ty * 8, w0 = tx * 16;
    const int ocg = blockIdx.y;
    const int ocBase = ocg * 64;

    const int tid  = threadIdx.x;
    const int warp = tid >> 5;
    const int oh = warp & 1;
    const int rw = warp >> 1;
    const int lane = tid & 31;
    const int g = lane >> 2;
    const int t = lane & 3;
    const int slot = ((g >> 1) << 3) | (t << 1) | (g & 1);

    if (tid < 64) s_bias[tid] = bias[ocBase + tid];

    float acc[2][2][2][4];
#pragma unroll
    for (int i = 0; i < 2; i++)
#pragma unroll
        for (int j = 0; j < 2; j++)
#pragma unroll
            for (int k = 0; k < 2; k++)
#pragma unroll
                for (int l = 0; l < 4; l++) acc[i][j][k][l] = 0.f;

    const uint32_t smbase = smem_addr_of(smu);
    const int wcnt = f16c ? 1152 : 2304;

    auto fill = [&](int q, int st) {
        const uint32_t sb = smbase + (uint32_t)st * STG_U32 * 4;
        const uint4* wH4 = (const uint4*)wH + (size_t)(q * 4 + ocg) * 1152;
        const uint4* wL4 = (const uint4*)wL + (size_t)(q * 4 + ocg) * 1152;
        for (int j = tid; j < wcnt; j += 256) {
            const uint4* src = (j < 1152) ? (wH4 + j) : (wL4 + (j - 1152));
            cp16(sb + j * 16, src, true);
        }
        for (int j = tid; j < 960; j += 256) {
            int slotc = j % 6;
            int rest = j / 6;
            int arr = rest & 1;
            int pr = rest >> 1;
            int p = pr / 10, r = pr % 10;
            int gh = h0 + r - 1;
            bool rowok = (gh >= 0) && (gh < H);
            int ghc = min(max(gh, 0), H - 1);
            size_t rowoff = ((size_t)n * 128 + q * 8 + p) * SUMHW + cOFF[s] + (size_t)ghc * W;
            const uint32_t* gsrc = arr ? inL : inH;
            uint32_t dstrow = sb + (uint32_t)((arr ? ST_IL : ST_IH) + (p * 10 + r) * IPAD) * 4;
            if (slotc < 4) {
                int c0 = slotc * 4;
                cp16(dstrow + (uint32_t)(4 + c0) * 4, gsrc + rowoff + w0 + c0, rowok);
            } else if (slotc == 4) {
                bool ok = rowok && (w0 > 0);
                cp4(dstrow + 3 * 4, gsrc + rowoff + (ok ? (w0 - 1) : w0), ok);
            } else {
                bool ok = rowok && (w0 + 16 < W);
                cp4(dstrow + 20 * 4, gsrc + rowoff + w0 + (ok ? 16 : 0), ok);
            }
        }
    };

    fill(0, 0);
    CP_COMMIT();

    for (int q = 0; q < 16; q++) {
        if (q < 15) { fill(q + 1, (q + 1) & 1); CP_COMMIT(); CP_WAIT(1); }
        else        { CP_WAIT(0); }
        __syncthreads();

        const uint32_t* sb = smu + (q & 1) * STG_U32;
        const uint4* s_w4H = (const uint4*)sb;
        const uint4* s_w4L = s_w4H + 1152;
        const uint32_t* s_iH = sb + ST_IH;
        const uint32_t* s_iL = sb + ST_IL;

#pragma unroll
        for (int kh = 0; kh < 3; kh++)
#pragma unroll
        for (int kw = 0; kw < 3; kw++) {
            const int tap = kh * 3 + kw;
            uint32_t bh[2][2][2], bl[2][2][2];
#pragma unroll
            for (int rr = 0; rr < 2; rr++) {
                const int row = 2 * rw + rr;
                const int ib0 = (t * 10 + row + kh) * IPAD + kw + 3 + g;
                const int ib1 = ((t + 4) * 10 + row + kh) * IPAD + kw + 3 + g;
#pragma unroll
                for (int p4 = 0; p4 < 2; p4++) {
                    bh[rr][p4][0] = s_iH[ib0 + p4 * 8];
                    bh[rr][p4][1] = s_iH[ib1 + p4 * 8];
                    bl[rr][p4][0] = s_iL[ib0 + p4 * 8];
                    bl[rr][p4][1] = s_iL[ib1 + p4 * 8];
                }
            }
#pragma unroll
            for (int o4l = 0; o4l < 2; o4l++) {
                const int o4g = oh * 2 + o4l;
                uint4 a4 = s_w4H[(tap * 4 + o4g) * 32 + slot];
                uint32_t ah[4] = {a4.x, a4.y, a4.z, a4.w};
                if (!f16c) {
                    uint4 b4 = s_w4L[(tap * 4 + o4g) * 32 + slot];
                    uint32_t al[4] = {b4.x, b4.y, b4.z, b4.w};
#pragma unroll
                    for (int rr = 0; rr < 2; rr++)
#pragma unroll
                        for (int p4 = 0; p4 < 2; p4++) {
                            mma_bf16(acc[o4l][rr][p4], ah, bh[rr][p4]);
                            mma_bf16(acc[o4l][rr][p4], ah, bl[rr][p4]);
                            mma_bf16(acc[o4l][rr][p4], al, bh[rr][p4]);
                        }
                } else {
#pragma unroll
                    for (int rr = 0; rr < 2; rr++)
#pragma unroll
                        for (int p4 = 0; p4 < 2; p4++) {
                            mma_f16(acc[o4l][rr][p4], ah, bh[rr][p4]);
                            mma_f16(acc[o4l][rr][p4], ah, bl[rr][p4]);
                        }
                }
            }
        }
        __syncthreads();
    }

    if (dstF) {
#pragma unroll
        for (int rr = 0; rr < 2; rr++) {
            const int ghout = h0 + 2 * rw + rr;
            if (ghout >= H) continue;
            float* dbase = dstF + (size_t)n * C * SUMHW + cOFF[s] + (size_t)ghout * W + w0;
#pragma unroll
            for (int o4l = 0; o4l < 2; o4l++) {
                int ocl = (oh * 2 + o4l) * 16 + g;
                float b0v = s_bias[ocl];
                float b1v = s_bias[ocl + 8];
#pragma unroll
                for (int p4 = 0; p4 < 2; p4++) {
                    int col = p4 * 8 + 2 * t;
                    float2 v0 = make_float2(fmaxf(acc[o4l][rr][p4][0] + b0v, 0.f),
                                            fmaxf(acc[o4l][rr][p4][1] + b0v, 0.f));
                    float2 v1 = make_float2(fmaxf(acc[o4l][rr][p4][2] + b1v, 0.f),
                                            fmaxf(acc[o4l][rr][p4][3] + b1v, 0.f));
                    *(float2*)(dbase + (size_t)(ocBase + ocl) * SUMHW + col) = v0;
                    *(float2*)(dbase + (size_t)(ocBase + ocl + 8) * SUMHW + col) = v1;
                }
            }
        }
    }
    if (dstH) {
#pragma unroll
        for (int rr = 0; rr < 2; rr++) {
            const int ghout = h0 + 2 * rw + rr;
            const size_t base = ((size_t)n * 128) * SUMHW + cOFF[s] + (size_t)ghout * W + w0;
#pragma unroll
            for (int o4l = 0; o4l < 2; o4l++) {
                int ocl = (oh * 2 + o4l) * 16 + g;
                float b0v = s_bias[ocl];
                float b1v = s_bias[ocl + 8];
                const size_t w2a = (size_t)((ocBase + ocl) >> 1) * SUMHW;
                const size_t w2b = (size_t)(((ocBase + ocl) >> 1) + 4) * SUMHW;
#pragma unroll
                for (int p4 = 0; p4 < 2; p4++) {
                    int col = p4 * 8 + 2 * t;
                    float v0 = fmaxf(acc[o4l][rr][p4][0] + b0v, 0.f);
                    float v1 = fmaxf(acc[o4l][rr][p4][1] + b0v, 0.f);
                    float v2 = fmaxf(acc[o4l][rr][p4][2] + b1v, 0.f);
                    float v3 = fmaxf(acc[o4l][rr][p4][3] + b1v, 0.f);
                    float p0 = __shfl_xor_sync(0xFFFFFFFFu, v0, 4);
                    float p1 = __shfl_xor_sync(0xFFFFFFFFu, v1, 4);
                    float p2 = __shfl_xor_sync(0xFFFFFFFFu, v2, 4);
                    float p3 = __shfl_xor_sync(0xFFFFFFFFu, v3, 4);
                    if (((g & 1) == 0) && ghout < H) {
                        uint32_t hw, lw;
                        if (sp16) split_pack_h(v0, p0, hw, lw);
                        else      split_pack(v0, p0, hw, lw);
                        dstH[base + w2a + col] = hw;  dstL[base + w2a + col] = lw;
                        if (sp16) split_pack_h(v1, p1, hw, lw);
                        else      split_pack(v1, p1, hw, lw);
                        dstH[base + w2a + col + 1] = hw;  dstL[base + w2a + col + 1] = lw;
                        if (sp16) split_pack_h(v2, p2, hw, lw);
                        else      split_pack(v2, p2, hw, lw);
                        dstH[base + w2b + col] = hw;  dstL[base + w2b + col] = lw;
                        if (sp16) split_pack_h(v3, p3, hw, lw);
                        else      split_pack(v3, p3, hw, lw);
                        dstH[base + w2b + col + 1] = hw;  dstL[base + w2b + col + 1] = lw;
                    }
                }
            }
        }
    }
}

// ---------------- dense GEMM (fp16 2-term) ----------------------------------
#define GIPAD 264
#define GST_U32 5248

// o_proj GEMM fused with hsum (fp16 2-term, hs out fp16)
__global__ __launch_bounds__(256, 2)
void gemm_oproj_hsum(const uint32_t* __restrict__ wH,
                     const uint32_t* __restrict__ bHg, const uint32_t* __restrict__ bLg,
                     const float* __restrict__ pproj,
                     uint32_t* __restrict__ hsH, uint32_t* __restrict__ hsL)
{
    __shared__ __align__(16) uint32_t gsm[2 * GST_U32];
    __shared__ float spp[KTOP * 64];

    const int s0 = blockIdx.x * 256;
    const int mg = blockIdx.y;
    const int n  = blockIdx.z;
    const int tid = threadIdx.x;
    const int warp = tid >> 5;
    const int lane = tid & 31;
    const int g = lane >> 2;
    const int t = lane & 3;
    const int slot = ((g >> 1) << 3) | (t << 1) | (g & 1);

    for (int i = tid; i < KTOP * 64; i += 256) {
        int k = i >> 6, dl = i & 63;
        spp[i] = pproj[((size_t)n * KTOP + k) * D + mg * 64 + dl];
    }

    float acc[4][4][4];
#pragma unroll
    for (int i = 0; i < 4; i++)
#pragma unroll
        for (int j = 0; j < 4; j++)
#pragma unroll
            for (int k = 0; k < 4; k++) acc[i][j][k] = 0.f;

    const uint32_t smbase = smem_addr_of(gsm);

    auto fill = [&](int q, int st) {
        const uint32_t sb = smbase + (uint32_t)st * GST_U32 * 4;
        const uint4* wH4 = (const uint4*)wH + (size_t)(q * 4 + mg) * 128;
        if (tid < 128) cp16(sb + tid * 16, wH4 + tid, true);
        for (int j = tid; j < 1024; j += 256) {
            int c = j & 63;
            int rest = j >> 6;
            int arr = rest & 1;
            int p = rest >> 1;
            int sx = s0 + c * 4;
            bool ok = sx < SUMHW;
            size_t off = ((size_t)n * 128 + q * 8 + p) * SUMHW + (ok ? sx : 0);
            const uint32_t* gsrc = arr ? bLg : bHg;
            uint32_t dst = sb + (uint32_t)(1024 + arr * 2112 + p * GIPAD + c * 4) * 4;
            cp16(dst, gsrc + off, ok);
        }
    };

    fill(0, 0);
    CP_COMMIT();

    for (int q = 0; q < 16; q++) {
        if (q < 15) { fill(q + 1, (q + 1) & 1); CP_COMMIT(); CP_WAIT(1); }
        else        { CP_WAIT(0); }
        __syncthreads();

        const uint32_t* sb = gsm + (q & 1) * GST_U32;
        const uint4* s_aH4 = (const uint4*)sb;
        const uint32_t* s_iH = sb + 1024;
        const uint32_t* s_iL = sb + 3136;

        uint32_t bh[4][2], bl[4][2];
        const int ib0 = t * GIPAD + warp * 32 + g;
        const int ib1 = (t + 4) * GIPAD + warp * 32 + g;
#pragma unroll
        for (int p4 = 0; p4 < 4; p4++) {
            bh[p4][0] = s_iH[ib0 + p4 * 8];
            bh[p4][1] = s_iH[ib1 + p4 * 8];
            bl[p4][0] = s_iL[ib0 + p4 * 8];
            bl[p4][1] = s_iL[ib1 + p4 * 8];
        }
#pragma unroll
        for (int o4 = 0; o4 < 4; o4++) {
            uint4 a4 = s_aH4[o4 * 32 + slot];
            uint32_t ah[4] = {a4.x, a4.y, a4.z, a4.w};
#pragma unroll
            for (int p4 = 0; p4 < 4; p4++) {
                mma_f16(acc[o4][p4], ah, bh[p4]);
                mma_f16(acc[o4][p4], ah, bl[p4]);
            }
        }
        __syncthreads();
    }

#pragma unroll
    for (int o4 = 0; o4 < 4; o4++) {
        const int m0l = o4 * 16 + g;
        const int m0  = mg * 64 + m0l;
        float pp0[KTOP], pp1[KTOP];
#pragma unroll
        for (int k = 0; k < KTOP; k++) {
            pp0[k] = spp[k * 64 + m0l];
            pp1[k] = spp[k * 64 + m0l + 8];
        }
        const size_t w2a = (size_t)(m0 >> 1) * SUMHW;
        const size_t w2b = (size_t)((m0 >> 1) + 4) * SUMHW;
        const size_t nb = (size_t)n * 128 * SUMHW;
#pragma unroll
        for (int p4 = 0; p4 < 4; p4++) {
            int sx = s0 + warp * 32 + p4 * 8 + 2 * t;
            float a0 = 0.f, a1 = 0.f, a2 = 0.f, a3 = 0.f;
#pragma unroll 4
            for (int k = 0; k < KTOP; k++) {
                a0 += fmaxf(acc[o4][p4][0] + pp0[k], 0.f);
                a1 += fmaxf(acc[o4][p4][1] + pp0[k], 0.f);
                a2 += fmaxf(acc[o4][p4][2] + pp1[k], 0.f);
                a3 += fmaxf(acc[o4][p4][3] + pp1[k], 0.f);
            }
            float q0 = __shfl_xor_sync(0xFFFFFFFFu, a0, 4);
            float q1 = __shfl_xor_sync(0xFFFFFFFFu, a1, 4);
            float q2 = __shfl_xor_sync(0xFFFFFFFFu, a2, 4);
            float q3 = __shfl_xor_sync(0xFFFFFFFFu, a3, 4);
            if (((g & 1) == 0) && sx < SUMHW) {
                uint32_t hw, lw;
                split_pack_h(a0, q0, hw, lw);
                hsH[nb + w2a + sx] = hw;      hsL[nb + w2a + sx] = lw;
                split_pack_h(a1, q1, hw, lw);
                hsH[nb + w2a + sx + 1] = hw;  hsL[nb + w2a + sx + 1] = lw;
                split_pack_h(a2, q2, hw, lw);
                hsH[nb + w2b + sx] = hw;      hsL[nb + w2b + sx] = lw;
                split_pack_h(a3, q3, hw, lw);
                hsH[nb + w2b + sx + 1] = hw;  hsL[nb + w2b + sx + 1] = lw;
            }
        }
    }
}

// rn2 GEMM with fused ol head: relu(W hs + b), then partial ol dot-products
// reduced over the block's 64 e via shfl, atomicAdd into out (pre-init to ol_b).
__global__ __launch_bounds__(256, 2)
void gemm_rn2_ol(const uint32_t* __restrict__ wH,
                 const uint32_t* __restrict__ bHg, const uint32_t* __restrict__ bLg,
                 const float* __restrict__ bias, const float* __restrict__ ol_w,
                 float* __restrict__ out)
{
    __shared__ __align__(16) uint32_t gsm[2 * GST_U32];
    __shared__ float s_olw[A][64];

    const int s0 = blockIdx.x * 256;
    const int mg = blockIdx.y;
    const int n  = blockIdx.z;
    const int tid = threadIdx.x;
    const int warp = tid >> 5;
    const int lane = tid & 31;
    const int g = lane >> 2;
    const int t = lane & 3;
    const int slot = ((g >> 1) << 3) | (t << 1) | (g & 1);

    if (tid < A * 64) s_olw[tid >> 6][tid & 63] = ol_w[(tid >> 6) * 256 + mg * 64 + (tid & 63)];

    float acc[4][4][4];
#pragma unroll
    for (int i = 0; i < 4; i++)
#pragma unroll
        for (int j = 0; j < 4; j++)
#pragma unroll
            for (int k = 0; k < 4; k++) acc[i][j][k] = 0.f;

    const uint32_t smbase = smem_addr_of(gsm);

    auto fill = [&](int q, int st) {
        const uint32_t sb = smbase + (uint32_t)st * GST_U32 * 4;
        const uint4* wH4 = (const uint4*)wH + (size_t)(q * 4 + mg) * 128;
        if (tid < 128) cp16(sb + tid * 16, wH4 + tid, true);
        for (int j = tid; j < 1024; j += 256) {
            int c = j & 63;
            int rest = j >> 6;
            int arr = rest & 1;
            int p = rest >> 1;
            int sx = s0 + c * 4;
            bool ok = sx < SUMHW;
            size_t off = ((size_t)n * 128 + q * 8 + p) * SUMHW + (ok ? sx : 0);
            const uint32_t* gsrc = arr ? bLg : bHg;
            uint32_t dst = sb + (uint32_t)(1024 + arr * 2112 + p * GIPAD + c * 4) * 4;
            cp16(dst, gsrc + off, ok);
        }
    };

    fill(0, 0);
    CP_COMMIT();

    for (int q = 0; q < 16; q++) {
        if (q < 15) { fill(q + 1, (q + 1) & 1); CP_COMMIT(); CP_WAIT(1); }
        else        { CP_WAIT(0); }
        __syncthreads();

        const uint32_t* sb = gsm + (q & 1) * GST_U32;
        const uint4* s_aH4 = (const uint4*)sb;
        const uint32_t* s_iH = sb + 1024;
        const uint32_t* s_iL = sb + 3136;

        uint32_t bh[4][2], bl[4][2];
        const int ib0 = t * GIPAD + warp * 32 + g;
        const int ib1 = (t + 4) * GIPAD + warp * 32 + g;
#pragma unroll
        for (int p4 = 0; p4 < 4; p4++) {
            bh[p4][0] = s_iH[ib0 + p4 * 8];
            bh[p4][1] = s_iH[ib1 + p4 * 8];
            bl[p4][0] = s_iL[ib0 + p4 * 8];
            bl[p4][1] = s_iL[ib1 + p4 * 8];
        }
#pragma unroll
        for (int o4 = 0; o4 < 4; o4++) {
            uint4 a4 = s_aH4[o4 * 32 + slot];
            uint32_t ah[4] = {a4.x, a4.y, a4.z, a4.w};
#pragma unroll
            for (int p4 = 0; p4 < 4; p4++) {
                mma_f16(acc[o4][p4], ah, bh[p4]);
                mma_f16(acc[o4][p4], ah, bl[p4]);
            }
        }
        __syncthreads();
    }

    // fused epilogue: relu + partial ol dot over this block's 64 e-values
    float pa[A][4][2];
#pragma unroll
    for (int a = 0; a < A; a++)
#pragma unroll
        for (int j = 0; j < 4; j++) { pa[a][j][0] = 0.f; pa[a][j][1] = 0.f; }

#pragma unroll
    for (int o4 = 0; o4 < 4; o4++) {
        const int m0l = o4 * 16 + g;
        const float b0v = bias[mg * 64 + m0l];
        const float b1v = bias[mg * 64 + m0l + 8];
        float wa0[A], wa1[A];
#pragma unroll
        for (int a = 0; a < A; a++) {
            wa0[a] = s_olw[a][m0l];
            wa1[a] = s_olw[a][m0l + 8];
        }
#pragma unroll
        for (int p4 = 0; p4 < 4; p4++) {
            float v0 = fmaxf(acc[o4][p4][0] + b0v, 0.f);
            float v1 = fmaxf(acc[o4][p4][1] + b0v, 0.f);
            float v2 = fmaxf(acc[o4][p4][2] + b1v, 0.f);
            float v3 = fmaxf(acc[o4][p4][3] + b1v, 0.f);
#pragma unroll
            for (int a = 0; a < A; a++) {
                pa[a][p4][0] += v0 * wa0[a] + v2 * wa1[a];
                pa[a][p4][1] += v1 * wa0[a] + v3 * wa1[a];
            }
        }
    }
    // reduce over g (lanes with same t: xor 4, 8, 16), then atomicAdd
#pragma unroll
    for (int p4 = 0; p4 < 4; p4++)
#pragma unroll
        for (int col = 0; col < 2; col++) {
            float sa[A];
#pragma unroll
            for (int a = 0; a < A; a++) {
                float v = pa[a][p4][col];
                v += __shfl_xor_sync(0xFFFFFFFFu, v, 4);
                v += __shfl_xor_sync(0xFFFFFFFFu, v, 8);
                v += __shfl_xor_sync(0xFFFFFFFFu, v, 16);
                sa[a] = v;
            }
            if (g == 0) {
                int sx = s0 + warp * 32 + p4 * 8 + 2 * t + col;
                if (sx < SUMHW) {
                    const int sc = scale_of(sx);
                    const int ploc = sx - cOFF[sc];
                    const int HW = cHW[sc];
#pragma unroll
                    for (int a = 0; a < A; a++)
                        atomicAdd(&out[cOLOG[sc] + ((size_t)n * A + a) * HW + ploc], sa[a]);
                }
            }
        }
}

// ---------------- ol bias init ----------------------------------------------
__global__ __launch_bounds__(256)
void ol_init(const float* __restrict__ ol_b, float* __restrict__ out)
{
    const int p = blockIdx.x * 256 + threadIdx.x;
    if (p >= SUMHW) return;
    const int a = blockIdx.y % A;
    const int n = blockIdx.y / A;
    const int s = scale_of(p);
    const int ploc = p - cOFF[s];
    const int HW = cHW[s];
    out[cOLOG[s] + ((size_t)n * A + a) * HW + ploc] = ol_b[a];
}

// ---------------- merged heads (person fp32 t2p; object fp16 sC) ------------
__global__ __launch_bounds__(256)
void heads_all(const float* __restrict__ t2p,
               const uint32_t* __restrict__ sCh, const uint32_t* __restrict__ sCl,
               const float* __restrict__ pl_w, const float* __restrict__ pl_b,
               const float* __restrict__ pd_w, const float* __restrict__ pd_b,
               const float* __restrict__ od_w, const float* __restrict__ od_b,
               float* __restrict__ out, float* __restrict__ cell)
{
    const int branch = blockIdx.y & 1;
    const int n = blockIdx.y >> 1;
    const int tid = threadIdx.x;
    __shared__ float swl[A * C];
    __shared__ float swd[BOXC * C];
    if (branch == 0) {
        for (int i = tid; i < A * C; i += 256) swl[i] = pl_w[i];
        for (int i = tid; i < BOXC * C; i += 256) swd[i] = pd_w[i];
    } else {
        for (int i = tid; i < BOXC * C; i += 256) swd[i] = od_w[i];
    }
    __syncthreads();

    const int p = blockIdx.x * 256 + tid;
    if (p >= SUMHW) return;
    const int s = scale_of(p);
    const int ploc = p - cOFF[s];
    const int HW = cHW[s];

    if (branch == 0) {
        const float* h = t2p + (size_t)n * C * SUMHW + p;
        float accl[A], accd[BOXC];
#pragma unroll
        for (int a = 0; a < A; a++) accl[a] = pl_b[a];
#pragma unroll
        for (int j = 0; j < BOXC; j++) accd[j] = pd_b[j];
        for (int c = 0; c < C; c++) {
            float v = h[(size_t)c * SUMHW];
#pragma unroll
            for (int a = 0; a < A; a++) accl[a] += swl[a * C + c] * v;
#pragma unroll
            for (int j = 0; j < BOXC; j++) accd[j] += swd[j * C + c] * v;
        }
        float m = accl[0];
#pragma unroll
        for (int a = 0; a < A; a++) {
            out[cPLOG[s] + ((size_t)n * A + a) * HW + ploc] = accl[a];
            m = fmaxf(m, accl[a]);
        }
#pragma unroll
        for (int j = 0; j < BOXC; j++)
            out[cPDEL[s] + ((size_t)n * BOXC + j) * HW + ploc] = accd[j];
        cell[(size_t)n * SUMHW + p] = m;
    } else {
        const uint32_t* hH = sCh + (size_t)n * 128 * SUMHW + p;
        const uint32_t* hL = sCl + (size_t)n * 128 * SUMHW + p;
        float accd[BOXC];
#pragma unroll
        for (int j = 0; j < BOXC; j++) accd[j] = od_b[j];
        for (int c2 = 0; c2 < 128; c2++) {
            float v0, v1;
            unsplit_h(hH[(size_t)c2 * SUMHW], hL[(size_t)c2 * SUMHW], v0, v1);
#pragma unroll
            for (int j = 0; j < BOXC; j++)
                accd[j] += swd[j * C + 2 * c2] * v0 + swd[j * C + 2 * c2 + 1] * v1;
        }
#pragma unroll
        for (int j = 0; j < BOXC; j++)
            out[cODEL[s] + ((size_t)n * BOXC + j) * HW + ploc] = accd[j];
    }
}

// ---------------- per-scale top-K (1024 threads, warp-shuffle reduce) -------
__global__ __launch_bounds__(1024)
void topk_flat(const float* __restrict__ cell, const float* __restrict__ hid,
               float* __restrict__ cand_hid, float* __restrict__ cand_sc)
{
    const int s = blockIdx.x;
    const int n = blockIdx.y;
    const int HW = cHW[s], off = cOFF[s];
    __shared__ float sc[10240];
    __shared__ float w_val[32];
    __shared__ int   w_idx[32];
    __shared__ int   sel[KTOP];
    const int tid = threadIdx.x;
    const int lane = tid & 31, wid = tid >> 5;

    for (int i = tid; i < HW; i += 1024)
        sc[i] = cell[(size_t)n * SUMHW + off + i];
    __syncthreads();

    for (int k = 0; k < KTOP; k++) {
        float best = -CUDART_INF_F;
        int bi = HW;
        for (int i = tid; i < HW; i += 1024) {
            float v = sc[i];
            if (v > best) { best = v; bi = i; }
        }
#pragma unroll
        for (int o = 16; o > 0; o >>= 1) {
            float v2 = __shfl_down_sync(0xFFFFFFFFu, best, o);
            int   i2 = __shfl_down_sync(0xFFFFFFFFu, bi, o);
            if (v2 > best || (v2 == best && i2 < bi)) { best = v2; bi = i2; }
        }
        if (lane == 0) { w_val[wid] = best; w_idx[wid] = bi; }
        __syncthreads();
        if (wid == 0) {
            best = w_val[lane]; bi = w_idx[lane];
#pragma unroll
            for (int o = 16; o > 0; o >>= 1) {
                float v2 = __shfl_down_sync(0xFFFFFFFFu, best, o);
                int   i2 = __shfl_down_sync(0xFFFFFFFFu, bi, o);
                if (v2 > best || (v2 == best && i2 < bi)) { best = v2; bi = i2; }
            }
            if (lane == 0) {
                sel[k] = bi;
                cand_sc[(size_t)n * 80 + s * KTOP + k] = best;
                sc[bi] = -CUDART_INF_F;
            }
        }
        __syncthreads();
    }
    for (int idx = tid; idx < C * KTOP; idx += 1024) {
        int c = idx / KTOP, k = idx % KTOP;
        cand_hid[((size_t)n * C + c) * 80 + s * KTOP + k] =
            hid[((size_t)n * C + c) * SUMHW + off + sel[k]];
    }
}

// ---------------- p_proj (inlines global top-K) ------------------------------
__global__ __launch_bounds__(256)
void pproj_kernel(const float* __restrict__ cand_hid, const float* __restrict__ cand_sc,
                  const float* __restrict__ rn1_w, const float* __restrict__ rn1_b,
                  float* __restrict__ pproj)
{
    const int k = blockIdx.x, n = blockIdx.y, d = threadIdx.x;
    __shared__ float sh[C];
    __shared__ int s_col;
    if (d == 0) {
        const float* sl = cand_sc + (size_t)n * 80;
        bool used[80];
        for (int i = 0; i < 80; i++) used[i] = false;
        int bi = 0;
        for (int kk = 0; kk <= k; kk++) {
            float best = -CUDART_INF_F; bi = 0;
            for (int i = 0; i < 80; i++)
                if (!used[i] && sl[i] > best) { best = sl[i]; bi = i; }
            used[bi] = true;
        }
        s_col = bi;
    }
    __syncthreads();
    const int col = s_col;
    sh[d] = cand_hid[((size_t)n * C + d) * 80 + col];
    __syncthreads();
    float acc = rn1_b[d];
    const float* wrow = rn1_w + (size_t)d * (2 * C) + C;   // Wp
    for (int c = 0; c < C; c++) acc += sh[c] * wrow[c];
    pproj[((size_t)n * KTOP + k) * D + d] = acc;
}

// ---------------------------- host orchestration ----------------------------
extern "C" void kernel_launch(void* const* d_in, const int* in_sizes, int n_in,
                              void* d_out, int out_size)
{
    const float* f0 = (const float*)d_in[0];
    const float* f1 = (const float*)d_in[1];
    const float* f2 = (const float*)d_in[2];
    const float* f3 = (const float*)d_in[3];
    const float* pc1_w = (const float*)d_in[4];
    const float* pc1_b = (const float*)d_in[5];
    const float* pc2_w = (const float*)d_in[6];
    const float* pc2_b = (const float*)d_in[7];
    const float* oc1_w = (const float*)d_in[8];
    const float* oc1_b = (const float*)d_in[9];
    const float* oc2_w = (const float*)d_in[10];
    const float* oc2_b = (const float*)d_in[11];
    const float* rn1_w = (const float*)d_in[12];
    const float* rn1_b = (const float*)d_in[13];
    const float* rn2_w = (const float*)d_in[14];
    const float* rn2_b = (const float*)d_in[15];
    const float* pl_w  = (const float*)d_in[16];
    const float* pl_b  = (const float*)d_in[17];
    const float* pd_w  = (const float*)d_in[18];
    const float* pd_b  = (const float*)d_in[19];
    const float* ol_w  = (const float*)d_in[20];
    const float* ol_b  = (const float*)d_in[21];
    const float* od_w  = (const float*)d_in[22];
    const float* od_b  = (const float*)d_in[23];
    float* out = (float*)d_out;

    float *t2p, *cell, *cand_hid, *cand_sc, *pproj;
    uint32_t *sAh, *sAl, *sAfh, *sAfl, *sBh, *sBl, *sDh, *sDl, *sCh, *sCl,
             *hsh, *hsl, *wsh, *wsl, *wdh, *wdl;
    cudaGetSymbolAddress((void**)&t2p, g_t2p);
    cudaGetSymbolAddress((void**)&cell, g_cell);
    cudaGetSymbolAddress((void**)&cand_hid, g_cand_hid);
    cudaGetSymbolAddress((void**)&cand_sc, g_cand_sc);
    cudaGetSymbolAddress((void**)&pproj, g_pproj);
    cudaGetSymbolAddress((void**)&sAh, g_sA_hi);
    cudaGetSymbolAddress((void**)&sAl, g_sA_lo);
    cudaGetSymbolAddress((void**)&sAfh, g_sAf_hi);
    cudaGetSymbolAddress((void**)&sAfl, g_sAf_lo);
    cudaGetSymbolAddress((void**)&sBh, g_sB_hi);
    cudaGetSymbolAddress((void**)&sBl, g_sB_lo);
    cudaGetSymbolAddress((void**)&sDh, g_sD_hi);
    cudaGetSymbolAddress((void**)&sDl, g_sD_lo);
    cudaGetSymbolAddress((void**)&sCh, g_sC_hi);
    cudaGetSymbolAddress((void**)&sCl, g_sC_lo);
    cudaGetSymbolAddress((void**)&hsh, g_hs_hi);
    cudaGetSymbolAddress((void**)&hsl, g_hs_lo);
    cudaGetSymbolAddress((void**)&wsh, g_wsp_hi);
    cudaGetSymbolAddress((void**)&wsl, g_wsp_lo);
    cudaGetSymbolAddress((void**)&wdh, g_wd_hi);
    cudaGetSymbolAddress((void**)&wdl, g_wd_lo);

    cudaFuncSetAttribute(conv3x3_dual,
                         cudaFuncAttributeMaxDynamicSharedMemorySize, CONV_SMEM);

    const dim3 convGrid(108, 4, NB * 2);
    const dim3 headGrid((SUMHW + 255) / 256, NB * 2);
    const dim3 gemmGrid(STILE, 4, NB);

    // ---- prep: split weights + feats ----
    split_w_conv<<<dim3((WSPL + 255) / 256, 4), 256>>>(pc1_w, pc2_w, oc1_w, oc2_w, wsh, wsl);
    split_w_dense<<<dim3((WDNS + 255) / 256, 2), 256>>>(rn1_w, rn2_w, 2 * C, D, wdh, wdl);
    split_feats_kernel<<<dim3((SUMHW + 255) / 256, 128, NB), 256>>>(
        f0, f1, f2, f3, sAh, sAl, sAfh, sAfl);

    // ---- layer 1: person bf16 3-term -> sB(bf16); object fp16 2-term -> sD(fp16)
    conv3x3_dual<<<convGrid, 256, CONV_SMEM>>>(
        sAh, sAl, sAfh, sAfl,
        wsh, wsl, wsh + 2 * WSPL, wsl + 2 * WSPL,
        pc1_b, oc1_b,
        nullptr, sBh, sBl,
        nullptr, sDh, sDl,
        /*flags0=*/0, /*flags1=*/3);
    // ---- layer 2: person bf16 -> t2p; object fp16 -> sC(fp16) only
    conv3x3_dual<<<convGrid, 256, CONV_SMEM>>>(
        sBh, sBl, sDh, sDl,
        wsh + WSPL, wsl + WSPL, wsh + 3 * WSPL, wsl + 3 * WSPL,
        pc2_b, oc2_b,
        t2p, nullptr, nullptr,
        nullptr, sCh, sCl,
        /*flags0=*/0, /*flags1=*/3);

    // ---- heads (person from t2p, object from sC split) ----
    heads_all<<<headGrid, 256>>>(t2p, sCh, sCl, pl_w, pl_b, pd_w, pd_b, od_w, od_b, out, cell);

    // ---- person relational path ----
    topk_flat<<<dim3(4, NB), 1024>>>(cell, t2p, cand_hid, cand_sc);
    pproj_kernel<<<dim3(KTOP, NB), 256>>>(cand_hid, cand_sc, rn1_w, rn1_b, pproj);

    // ---- object relational path (fp16 2-term GEMMs, ol fused into rn2) ----
    ol_init<<<dim3(STILE, NB * A), 256>>>(ol_b, out);
    gemm_oproj_hsum<<<gemmGrid, 256>>>(wdh, sCh, sCl, pproj, hsh, hsl);
    gemm_rn2_ol<<<gemmGrid, 256>>>(wdh + WDNS, hsh, hsl, rn2_b, ol_w, out);

    (void)in_sizes; (void)n_in; (void)out_size;
}